// round 15
// baseline (speedup 1.0000x reference)
#include <cuda_runtime.h>
#include <cstdint>

#define N_USER   150000
#define M_ITEM   30000
#define N_NODES  180000
#define DIM      64
#define BATCH    1024
#define AUX_LD   10246
#define XCOLS    640
#define MAXE     1300000

// ---------------- scratch (static device memory; no allocs allowed) --------
__device__ float g_embB[(size_t)N_NODES * DIM];   // e1 (full)
__device__ float g_embC[(size_t)N_NODES * DIM];   // e2 (valid at flag2 rows only)
__device__ float g_e3  [2 * BATCH * DIM];         // e3 at batch positions
__device__ float g_X   [BATCH * XCOLS];
__device__ float g_H1  [BATCH * DIM];
__device__ float g_sums[BATCH * 3];
__device__ unsigned char g_flag2[N_NODES];
__device__ int   g_nlist2[N_NODES];
__device__ int   g_cnt[4];
// CSR
__device__ int   g_deg   [N_NODES];
__device__ int   g_rowptr[N_NODES + 1];
__device__ int   g_cursor[N_NODES];
__device__ int   g_csr_col[MAXE];
__device__ float g_csr_val[MAXE];
__device__ int   g_bsum [256];
__device__ int   g_boffs[256];

// vectorized no-return global reductions (sm_90+)
__device__ __forceinline__ void red_add_v2(float* p, float a, float b) {
    asm volatile("red.global.add.v2.f32 [%0], {%1,%2};"
                 :: "l"(p), "f"(a), "f"(b) : "memory");
}
__device__ __forceinline__ unsigned f2tf32(float f) {
    unsigned u;
    asm("cvt.rna.tf32.f32 %0, %1;" : "=r"(u) : "f"(f));
    return u;
}

// ====== fused: multi-hot row sums + zero(X[:,64:256), deg, flag2, cnt) =====
__global__ void rowsums_zero_kernel(const int* __restrict__ aux, float* __restrict__ sums,
                                    float* __restrict__ X, int* __restrict__ deg,
                                    unsigned char* __restrict__ flag2, int* __restrict__ cnt) {
    int b = blockIdx.x;            // 1024
    int t = threadIdx.x;           // 256
    const int* a = aux + (size_t)b * AUX_LD;
    float s0 = 0.f, s1 = 0.f, s2 = 0.f;
    for (int j = 1 + t;    j < 26;    j += 256) s0 += (float)a[j];
    for (int j = 26 + t;   j < 2212;  j += 256) s1 += (float)a[j];
    for (int j = 2212 + t; j < 10242; j += 256) s2 += (float)a[j];
    __shared__ float sd0[256], sd1[256], sd2[256];
    sd0[t] = s0; sd1[t] = s1; sd2[t] = s2;
    __syncthreads();
    for (int off = 128; off > 0; off >>= 1) {
        if (t < off) { sd0[t] += sd0[t + off]; sd1[t] += sd1[t + off]; sd2[t] += sd2[t + off]; }
        __syncthreads();
    }
    if (t == 0) {
        sums[b * 3 + 0] = sd0[0];
        sums[b * 3 + 1] = sd1[0];
        sums[b * 3 + 2] = sd2[0];
    }
    // zero X[b, 64:256)
    if (t < 192) X[(size_t)b * XCOLS + 64 + t] = 0.f;
    // zero deg / flag2 slices (1024 blocks x 176 covers 180224 >= N_NODES)
    if (t < 176) {
        int idx = b * 176 + t;
        if (idx < N_NODES) { deg[idx] = 0; flag2[idx] = 0; }
    }
    if (b == 0 && t < 4) cnt[t] = 0;
}

// ================= CSR build =================
__global__ void hist_kernel(const int* __restrict__ row, int nnz, int* __restrict__ deg) {
    int e = blockIdx.x * blockDim.x + threadIdx.x;
    if (e < nnz) atomicAdd(&deg[__ldg(row + e)], 1);
}

__global__ void bsum_kernel(const int* __restrict__ deg, int* __restrict__ bsum) {
    int b = blockIdx.x, t = threadIdx.x;
    int i0 = b * 1024 + t * 4;
    int s = 0;
    #pragma unroll
    for (int k = 0; k < 4; k++) {
        int i = i0 + k;
        if (i < N_NODES) s += deg[i];
    }
    __shared__ int sd[256];
    sd[t] = s;
    __syncthreads();
    for (int off = 128; off > 0; off >>= 1) {
        if (t < off) sd[t] += sd[t + off];
        __syncthreads();
    }
    if (t == 0) bsum[b] = sd[0];
}

__global__ void bscan_kernel(const int* __restrict__ bsum, int* __restrict__ boffs,
                             int nb, int nnz, int* __restrict__ rowptr) {
    int t = threadIdx.x;
    __shared__ int s[256];
    int orig = (t < nb) ? bsum[t] : 0;
    s[t] = orig;
    __syncthreads();
    for (int off = 1; off < 256; off <<= 1) {
        int v = (t >= off) ? s[t - off] : 0;
        __syncthreads();
        s[t] += v;
        __syncthreads();
    }
    boffs[t] = s[t] - orig;
    if (t == 0) rowptr[N_NODES] = nnz;
}

__global__ void scan_kernel(const int* __restrict__ deg, const int* __restrict__ boffs,
                            int* __restrict__ rowptr, int* __restrict__ cursor) {
    int t = threadIdx.x;
    int lane = t & 31, wid = t >> 5;
    int i0 = blockIdx.x * 1024 + t * 4;
    int d0 = (i0 + 0 < N_NODES) ? deg[i0 + 0] : 0;
    int d1 = (i0 + 1 < N_NODES) ? deg[i0 + 1] : 0;
    int d2 = (i0 + 2 < N_NODES) ? deg[i0 + 2] : 0;
    int d3 = (i0 + 3 < N_NODES) ? deg[i0 + 3] : 0;
    int ts = d0 + d1 + d2 + d3;
    int x = ts;
    #pragma unroll
    for (int off = 1; off < 32; off <<= 1) {
        int y = __shfl_up_sync(0xffffffffu, x, off);
        if (lane >= off) x += y;
    }
    int lane_excl = x - ts;
    __shared__ int wtot[8], woff[8];
    if (lane == 31) wtot[wid] = x;
    __syncthreads();
    if (t == 0) {
        int r = 0;
        #pragma unroll
        for (int k = 0; k < 8; k++) { woff[k] = r; r += wtot[k]; }
    }
    __syncthreads();
    int p = boffs[blockIdx.x] + woff[wid] + lane_excl;
    if (i0 + 0 < N_NODES) { rowptr[i0 + 0] = p; cursor[i0 + 0] = p; } p += d0;
    if (i0 + 1 < N_NODES) { rowptr[i0 + 1] = p; cursor[i0 + 1] = p; } p += d1;
    if (i0 + 2 < N_NODES) { rowptr[i0 + 2] = p; cursor[i0 + 2] = p; } p += d2;
    if (i0 + 3 < N_NODES) { rowptr[i0 + 3] = p; cursor[i0 + 3] = p; }
}

__global__ void scatter_kernel(const int* __restrict__ row, const int* __restrict__ col,
                               const float* __restrict__ val, int nnz,
                               int* __restrict__ cursor,
                               int* __restrict__ ccol, float* __restrict__ cval) {
    int e = blockIdx.x * blockDim.x + threadIdx.x;
    if (e >= nnz) return;
    int pos = atomicAdd(&cursor[__ldg(row + e)], 1);
    ccol[pos] = __ldg(col + e);
    cval[pos] = __ldg(val + e);
}

// ================= pull SpMM =================
__global__ void pull_all_kernel(const float* __restrict__ user_rel,
                                const float* __restrict__ item_rel,
                                const int* __restrict__ rowptr,
                                const int* __restrict__ ccol, const float* __restrict__ cval,
                                float* __restrict__ dst) {
    int w = (blockIdx.x * blockDim.x + threadIdx.x) >> 5;
    int lane = threadIdx.x & 31;
    if (w >= N_NODES) return;
    int s = __ldg(rowptr + w), e = __ldg(rowptr + w + 1);
    float ax = 0.f, ay = 0.f;
    for (int j = s; j < e; j++) {
        int c = __ldg(ccol + j);
        float v = __ldg(cval + j);
        const float* src = (c < N_USER) ? user_rel + (size_t)c * DIM
                                        : item_rel + (size_t)(c - N_USER) * DIM;
        float2 x = *reinterpret_cast<const float2*>(src + lane * 2);
        ax += v * x.x; ay += v * x.y;
    }
    *reinterpret_cast<float2*>(dst + (size_t)w * DIM + lane * 2) = make_float2(ax, ay);
}

__global__ void mark2_kernel(const int* __restrict__ uid, const int* __restrict__ iid,
                             const int* __restrict__ rowptr, const int* __restrict__ ccol,
                             unsigned char* __restrict__ flag2) {
    int w = (blockIdx.x * blockDim.x + threadIdx.x) >> 5;
    int lane = threadIdx.x & 31;
    if (w >= 2 * BATCH) return;
    int node = (w < BATCH) ? __ldg(uid + w) : N_USER + __ldg(iid + w - BATCH);
    if (lane == 0) flag2[node] = 1;
    int s = __ldg(rowptr + node), e = __ldg(rowptr + node + 1);
    for (int j = s + lane; j < e; j += 32) flag2[__ldg(ccol + j)] = 1;
}

__global__ void node_compact_kernel(const unsigned char* __restrict__ flag2,
                                    int* __restrict__ list, int* __restrict__ count) {
    int n = blockIdx.x * blockDim.x + threadIdx.x;
    bool act = (n < N_NODES) && (flag2[n] != 0);
    unsigned mask = __ballot_sync(0xffffffffu, act);
    int c = __popc(mask);
    int lane = threadIdx.x & 31;
    int base = 0;
    if (lane == 0 && c) base = atomicAdd(count, c);
    base = __shfl_sync(0xffffffffu, base, 0);
    if (act) list[base + __popc(mask & ((1u << lane) - 1))] = n;
}

__global__ void pull_list_kernel(const float* __restrict__ src, float* __restrict__ dst,
                                 const int* __restrict__ rowptr,
                                 const int* __restrict__ ccol, const float* __restrict__ cval,
                                 const int* __restrict__ list, const int* __restrict__ count) {
    int nw = (gridDim.x * blockDim.x) >> 5;
    int lane = threadIdx.x & 31;
    int n = *count;
    for (int w = (blockIdx.x * blockDim.x + threadIdx.x) >> 5; w < n; w += nw) {
        int r = __ldg(list + w);
        int s = __ldg(rowptr + r), e = __ldg(rowptr + r + 1);
        float ax = 0.f, ay = 0.f;
        for (int j = s; j < e; j++) {
            int c = __ldg(ccol + j);
            float v = __ldg(cval + j);
            float2 x = *reinterpret_cast<const float2*>(src + (size_t)c * DIM + lane * 2);
            ax += v * x.x; ay += v * x.y;
        }
        *reinterpret_cast<float2*>(dst + (size_t)r * DIM + lane * 2) = make_float2(ax, ay);
    }
}

__global__ void pull_batch_kernel(const int* __restrict__ uid, const int* __restrict__ iid,
                                  const float* __restrict__ src,
                                  const int* __restrict__ rowptr,
                                  const int* __restrict__ ccol, const float* __restrict__ cval,
                                  float* __restrict__ e3) {
    int w = (blockIdx.x * blockDim.x + threadIdx.x) >> 5;
    int lane = threadIdx.x & 31;
    if (w >= 2 * BATCH) return;
    int node = (w < BATCH) ? __ldg(uid + w) : N_USER + __ldg(iid + w - BATCH);
    int s = __ldg(rowptr + node), e = __ldg(rowptr + node + 1);
    float ax = 0.f, ay = 0.f;
    for (int j = s; j < e; j++) {
        int c = __ldg(ccol + j);
        float v = __ldg(cval + j);
        float2 x = *reinterpret_cast<const float2*>(src + (size_t)c * DIM + lane * 2);
        ax += v * x.x; ay += v * x.y;
    }
    *reinterpret_cast<float2*>(e3 + (size_t)w * DIM + lane * 2) = make_float2(ax, ay);
}

// ------- multi-hot GEMM via tf32 tensor cores (R12-proven): X += (A@W)/rs --
__global__ __launch_bounds__(256)
void mh_gemm_tc_kernel(const int* __restrict__ aux, int colIn, int K, int tilesPerBlock,
                       const float* __restrict__ W,
                       const float* __restrict__ sums, int sumIdx,
                       float* __restrict__ X, int colOut) {
    __shared__ unsigned xs[64][36];   // A tile, [row][k]
    __shared__ unsigned ws[32][72];   // W tile, [k][n]
    int t = threadIdx.x;
    int wrp = t >> 5, lane = t & 31;
    int wr = wrp >> 1;
    int wc = wrp & 1;
    int rowBase = blockIdx.x * 64;
    int kStart = blockIdx.y * tilesPerBlock * 32;
    int kEnd   = min(K, kStart + tilesPerBlock * 32);

    float acc[4][4] = {};

    for (int k0 = kStart; k0 < kEnd; k0 += 32) {
        #pragma unroll
        for (int i = 0; i < 8; i++) {
            int l = t + 256 * i;
            int kk = l & 31, rr = l >> 5;
            int kg = k0 + kk;
            float a = (kg < K) ? (float)aux[(size_t)(rowBase + rr) * AUX_LD + colIn + kg] : 0.f;
            xs[rr][kk] = __float_as_uint(a);   // 0/1 exact in tf32
        }
        #pragma unroll
        for (int i = 0; i < 8; i++) {
            int l = t + 256 * i;
            int cc = l & 63, kk = l >> 6;
            int kg = k0 + kk;
            ws[kk][cc] = (kg < K) ? f2tf32(W[(size_t)kg * 64 + cc]) : 0u;
        }
        __syncthreads();
        int ar0 = wr * 16 + (lane >> 2);
        int kc  = lane & 3;
        #pragma unroll
        for (int ks = 0; ks < 32; ks += 8) {
            unsigned a0 = xs[ar0    ][ks + kc];
            unsigned a1 = xs[ar0 + 8][ks + kc];
            unsigned a2 = xs[ar0    ][ks + kc + 4];
            unsigned a3 = xs[ar0 + 8][ks + kc + 4];
            #pragma unroll
            for (int nt = 0; nt < 4; nt++) {
                int n = wc * 32 + nt * 8 + (lane >> 2);
                unsigned b0 = ws[ks + kc    ][n];
                unsigned b1 = ws[ks + kc + 4][n];
                asm volatile(
                    "mma.sync.aligned.m16n8k8.row.col.f32.tf32.tf32.f32 "
                    "{%0,%1,%2,%3}, {%4,%5,%6,%7}, {%8,%9}, {%0,%1,%2,%3};"
                    : "+f"(acc[nt][0]), "+f"(acc[nt][1]), "+f"(acc[nt][2]), "+f"(acc[nt][3])
                    : "r"(a0), "r"(a1), "r"(a2), "r"(a3), "r"(b0), "r"(b1));
            }
        }
        __syncthreads();
    }

    int r0 = rowBase + wr * 16 + (lane >> 2);
    int r1 = r0 + 8;
    float rn0 = 1.0f / sums[r0 * 3 + sumIdx];
    float rn1 = 1.0f / sums[r1 * 3 + sumIdx];
    #pragma unroll
    for (int nt = 0; nt < 4; nt++) {
        int c = colOut + wc * 32 + nt * 8 + 2 * (lane & 3);
        red_add_v2(&X[(size_t)r0 * XCOLS + c], acc[nt][0] * rn0, acc[nt][1] * rn0);
        red_add_v2(&X[(size_t)r1 * XCOLS + c], acc[nt][2] * rn1, acc[nt][3] * rn1);
    }
}

// ------- fc1: full-K fp32 GEMM + fused bias+ReLU, direct store -------------
__global__ __launch_bounds__(256)
void fc1_kernel(const float* __restrict__ A, int lda, int K,
                const float* __restrict__ W, const float* __restrict__ bias,
                float* __restrict__ out, int ldo) {
    __shared__ float xs[32][68];
    __shared__ float ws[32][64];
    int t  = threadIdx.x;
    int tx = t & 15;
    int ty = t >> 4;
    int rowBase = blockIdx.x * 64;

    float acc[4][4] = {};
    for (int k0 = 0; k0 < K; k0 += 32) {
        #pragma unroll
        for (int i = 0; i < 8; i++) {
            int l = t + 256 * i;
            int kk = l & 31, rr = l >> 5;
            xs[kk][rr] = A[(size_t)(rowBase + rr) * lda + k0 + kk];
        }
        #pragma unroll
        for (int i = 0; i < 8; i++) {
            int l = t + 256 * i;
            int cc = l & 63, kk = l >> 6;
            ws[kk][cc] = W[(size_t)(k0 + kk) * 64 + cc];
        }
        __syncthreads();
        #pragma unroll
        for (int k = 0; k < 32; k++) {
            float4 wv = *reinterpret_cast<float4*>(&ws[k][tx * 4]);
            float4 av = *reinterpret_cast<float4*>(&xs[k][ty * 4]);
            acc[0][0] += av.x * wv.x; acc[0][1] += av.x * wv.y; acc[0][2] += av.x * wv.z; acc[0][3] += av.x * wv.w;
            acc[1][0] += av.y * wv.x; acc[1][1] += av.y * wv.y; acc[1][2] += av.y * wv.z; acc[1][3] += av.y * wv.w;
            acc[2][0] += av.z * wv.x; acc[2][1] += av.z * wv.y; acc[2][2] += av.z * wv.z; acc[2][3] += av.z * wv.w;
            acc[3][0] += av.w * wv.x; acc[3][1] += av.w * wv.y; acc[3][2] += av.w * wv.z; acc[3][3] += av.w * wv.w;
        }
        __syncthreads();
    }
    float4 bv = *reinterpret_cast<const float4*>(bias + tx * 4);
    #pragma unroll
    for (int r = 0; r < 4; r++) {
        int row = rowBase + ty * 4 + r;
        float4 v;
        v.x = fmaxf(acc[r][0] + bv.x, 0.f);
        v.y = fmaxf(acc[r][1] + bv.y, 0.f);
        v.z = fmaxf(acc[r][2] + bv.z, 0.f);
        v.w = fmaxf(acc[r][3] + bv.w, 0.f);
        *reinterpret_cast<float4*>(&out[(size_t)row * ldo + tx * 4]) = v;
    }
}

// ------- fc2 + out: H2=relu(H1@W2+b2) in smem, then out = H2@ow + ob -------
__global__ __launch_bounds__(256)
void fc2_out_kernel(const float* __restrict__ A,
                    const float* __restrict__ W, const float* __restrict__ bias,
                    const float* __restrict__ ow, const float* __restrict__ ob,
                    float* __restrict__ out) {
    __shared__ float xs[32][68];
    __shared__ float ws[32][64];
    __shared__ float h2[64][68];
    int t  = threadIdx.x;
    int tx = t & 15;
    int ty = t >> 4;
    int rowBase = blockIdx.x * 64;

    float acc[4][4] = {};
    for (int k0 = 0; k0 < 64; k0 += 32) {
        #pragma unroll
        for (int i = 0; i < 8; i++) {
            int l = t + 256 * i;
            int kk = l & 31, rr = l >> 5;
            xs[kk][rr] = A[(size_t)(rowBase + rr) * 64 + k0 + kk];
        }
        #pragma unroll
        for (int i = 0; i < 8; i++) {
            int l = t + 256 * i;
            int cc = l & 63, kk = l >> 6;
            ws[kk][cc] = W[(size_t)(k0 + kk) * 64 + cc];
        }
        __syncthreads();
        #pragma unroll
        for (int k = 0; k < 32; k++) {
            float4 wv = *reinterpret_cast<float4*>(&ws[k][tx * 4]);
            float4 av = *reinterpret_cast<float4*>(&xs[k][ty * 4]);
            acc[0][0] += av.x * wv.x; acc[0][1] += av.x * wv.y; acc[0][2] += av.x * wv.z; acc[0][3] += av.x * wv.w;
            acc[1][0] += av.y * wv.x; acc[1][1] += av.y * wv.y; acc[1][2] += av.y * wv.z; acc[1][3] += av.y * wv.w;
            acc[2][0] += av.z * wv.x; acc[2][1] += av.z * wv.y; acc[2][2] += av.z * wv.z; acc[2][3] += av.z * wv.w;
            acc[3][0] += av.w * wv.x; acc[3][1] += av.w * wv.y; acc[3][2] += av.w * wv.z; acc[3][3] += av.w * wv.w;
        }
        __syncthreads();
    }
    float4 bv = *reinterpret_cast<const float4*>(bias + tx * 4);
    #pragma unroll
    for (int r = 0; r < 4; r++) {
        int row = ty * 4 + r;
        h2[row][tx * 4 + 0] = fmaxf(acc[r][0] + bv.x, 0.f);
        h2[row][tx * 4 + 1] = fmaxf(acc[r][1] + bv.y, 0.f);
        h2[row][tx * 4 + 2] = fmaxf(acc[r][2] + bv.z, 0.f);
        h2[row][tx * 4 + 3] = fmaxf(acc[r][3] + bv.w, 0.f);
    }
    __syncthreads();
    // final dot: 64 rows, each handled by 4 threads (t = row*4 + q)
    if (t < 256) {
        int row = t >> 2, q = t & 3;
        float s = 0.f;
        #pragma unroll
        for (int c = 0; c < 16; c++) {
            int col = q * 16 + c;
            s += h2[row][col] * __ldg(ow + col);
        }
        // reduce 4 partials via shfl (lanes row*4+q are contiguous in a warp)
        s += __shfl_down_sync(0xffffffffu, s, 1);
        s += __shfl_down_sync(0xffffffffu, s, 2);
        if (q == 0) out[rowBase + row] = s + __ldg(ob);
    }
}

// ---------------- gathers: tables + LightGCN sum (emb0+e1+e2+e3)/4 --------
__global__ void gather_kernel(const int* __restrict__ aux,
                              const int* __restrict__ uid, const int* __restrict__ iid,
                              const float* __restrict__ rate_tab,
                              const float* __restrict__ gender_tab,
                              const float* __restrict__ age_tab,
                              const float* __restrict__ occ_tab,
                              const float* __restrict__ area_tab,
                              const float* __restrict__ user_rel,
                              const float* __restrict__ item_rel,
                              const float* __restrict__ e1,
                              const float* __restrict__ e2,
                              const float* __restrict__ e3,
                              float* __restrict__ X) {
    int b = blockIdx.x;
    int d = threadIdx.x;   // 64
    const int* a = aux + (size_t)b * AUX_LD;
    float* xr = X + (size_t)b * XCOLS;
    xr[0   + d] = rate_tab  [(size_t)a[0]     * 64 + d];
    xr[256 + d] = gender_tab[(size_t)a[10242] * 64 + d];
    xr[320 + d] = age_tab   [(size_t)a[10243] * 64 + d];
    xr[384 + d] = occ_tab   [(size_t)a[10244] * 64 + d];
    xr[448 + d] = area_tab  [(size_t)a[10245] * 64 + d];
    int u  = uid[b];
    int it = iid[b];
    size_t un  = (size_t)u * 64 + d;
    size_t in_ = ((size_t)N_USER + it) * 64 + d;
    xr[512 + d] = 0.25f * (user_rel[un] + e1[un] + e2[un] + e3[(size_t)b * 64 + d]);
    xr[576 + d] = 0.25f * (item_rel[(size_t)it * 64 + d] + e1[in_] + e2[in_]
                           + e3[(size_t)(BATCH + b) * 64 + d]);
}

// ---------------- launch ---------------------------------------------------
extern "C" void kernel_launch(void* const* d_in, const int* in_sizes, int n_in,
                              void* d_out, int out_size) {
    const int*   aux       = (const int*)  d_in[0];
    const int*   user_ids  = (const int*)  d_in[1];
    const int*   item_ids  = (const int*)  d_in[2];
    const int*   grow      = (const int*)  d_in[3];
    const int*   gcol      = (const int*)  d_in[4];
    const float* gval      = (const float*)d_in[5];
    const float* rate_tab  = (const float*)d_in[6];
    const float* genre_W   = (const float*)d_in[7];
    const float* director_W= (const float*)d_in[8];
    const float* actor_W   = (const float*)d_in[9];
    const float* gender_tab= (const float*)d_in[10];
    const float* age_tab   = (const float*)d_in[11];
    const float* occ_tab   = (const float*)d_in[12];
    const float* area_tab  = (const float*)d_in[13];
    const float* user_rel  = (const float*)d_in[14];
    const float* item_rel  = (const float*)d_in[15];
    const float* fc1_W     = (const float*)d_in[16];
    const float* fc1_b     = (const float*)d_in[17];
    const float* fc2_W     = (const float*)d_in[18];
    const float* fc2_b     = (const float*)d_in[19];
    const float* out_W     = (const float*)d_in[20];
    const float* out_b     = (const float*)d_in[21];
    int nnz = in_sizes[3];

    float *embB, *embC, *e3, *X, *H1, *sums;
    unsigned char* flag2;
    int *nlist2, *cnt, *deg, *rowptr, *cursor, *ccol, *bsum, *boffs;
    float* cval;
    cudaGetSymbolAddress((void**)&embB,  g_embB);
    cudaGetSymbolAddress((void**)&embC,  g_embC);
    cudaGetSymbolAddress((void**)&e3,    g_e3);
    cudaGetSymbolAddress((void**)&X,     g_X);
    cudaGetSymbolAddress((void**)&H1,    g_H1);
    cudaGetSymbolAddress((void**)&sums,  g_sums);
    cudaGetSymbolAddress((void**)&flag2, g_flag2);
    cudaGetSymbolAddress((void**)&nlist2,g_nlist2);
    cudaGetSymbolAddress((void**)&cnt,   g_cnt);
    cudaGetSymbolAddress((void**)&deg,   g_deg);
    cudaGetSymbolAddress((void**)&rowptr,g_rowptr);
    cudaGetSymbolAddress((void**)&cursor,g_cursor);
    cudaGetSymbolAddress((void**)&ccol,  g_csr_col);
    cudaGetSymbolAddress((void**)&cval,  g_csr_val);
    cudaGetSymbolAddress((void**)&bsum,  g_bsum);
    cudaGetSymbolAddress((void**)&boffs, g_boffs);

    const int EB = (nnz + 255) / 256;
    const int NB = (N_NODES + 1023) / 1024;   // 176

    // --- fused rowsums + all zeroing (replaces 4 memsets + rowsums) ---
    rowsums_zero_kernel<<<BATCH, 256>>>(aux, sums, X, deg, flag2, cnt);

    // --- multi-hot GEMMs (tf32 TC; R12-proven splits) ---
    mh_gemm_tc_kernel<<<dim3(16, 1),  256>>>(aux, 1,    25,   1, genre_W,    sums, 0, X, 64);
    mh_gemm_tc_kernel<<<dim3(16, 14), 256>>>(aux, 26,   2186, 5, director_W, sums, 1, X, 128);
    mh_gemm_tc_kernel<<<dim3(16, 28), 256>>>(aux, 2212, 8030, 9, actor_W,    sums, 2, X, 192);

    // --- CSR build (deg/cnt pre-zeroed by rowsums_zero) ---
    hist_kernel<<<EB, 256>>>(grow, nnz, deg);
    bsum_kernel<<<NB, 256>>>(deg, bsum);
    bscan_kernel<<<1, 256>>>(bsum, boffs, NB, nnz, rowptr);
    scan_kernel<<<NB, 256>>>(deg, boffs, rowptr, cursor);
    scatter_kernel<<<EB, 256>>>(grow, gcol, gval, nnz, cursor, ccol, cval);

    // --- flag2 = batch ∪ neighbors(batch); compact node list ---
    mark2_kernel<<<(2 * BATCH * 32 + 255) / 256, 256>>>(user_ids, item_ids, rowptr, ccol, flag2);
    node_compact_kernel<<<(N_NODES + 255) / 256, 256>>>(flag2, nlist2, cnt + 0);

    // --- LightGCN: 3 pull layers ---
    pull_all_kernel<<<(N_NODES * 32 + 255) / 256, 256>>>(user_rel, item_rel,
                                                         rowptr, ccol, cval, embB);
    pull_list_kernel<<<2048, 256>>>(embB, embC, rowptr, ccol, cval, nlist2, cnt + 0);
    pull_batch_kernel<<<(2 * BATCH * 32 + 255) / 256, 256>>>(user_ids, item_ids, embC,
                                                             rowptr, ccol, cval, e3);

    // --- assemble X ---
    gather_kernel<<<BATCH, 64>>>(aux, user_ids, item_ids, rate_tab, gender_tab,
                                 age_tab, occ_tab, area_tab,
                                 user_rel, item_rel, embB, embC, e3, X);

    // --- MLP: fc1 (fused bias+relu), fc2+out fused ---
    fc1_kernel<<<16, 256>>>(X, XCOLS, XCOLS, fc1_W, fc1_b, H1, 64);
    fc2_out_kernel<<<16, 256>>>(H1, fc2_W, fc2_b, out_W, out_b, (float*)d_out);
}

// round 17
// speedup vs baseline: 1.2668x; 1.2668x over previous
#include <cuda_runtime.h>
#include <cstdint>

#define N_USER   150000
#define M_ITEM   30000
#define N_NODES  180000
#define DIM      64
#define BATCH    1024
#define AUX_LD   10246
#define XCOLS    640
#define MAXE     1300000

// ---------------- scratch (static device memory; no allocs allowed) --------
__device__ float g_embB[(size_t)N_NODES * DIM];   // e1 (full)
__device__ float g_embC[(size_t)N_NODES * DIM];   // e2 (valid at flag2 rows only)
__device__ float g_e3  [2 * BATCH * DIM];         // e3 at batch positions
__device__ float g_X   [BATCH * XCOLS];
__device__ float g_H1  [BATCH * DIM];
__device__ float g_H2  [BATCH * DIM];
__device__ float g_sums[BATCH * 3];
__device__ unsigned char g_flag2[N_NODES];
__device__ int   g_nlist2[N_NODES];
__device__ int   g_cnt[4];
// CSR
__device__ int   g_deg   [N_NODES];
__device__ int   g_rowptr[N_NODES + 1];
__device__ int   g_cursor[N_NODES];
__device__ int   g_csr_col[MAXE];
__device__ float g_csr_val[MAXE];
__device__ int   g_bsum [256];
__device__ int   g_boffs[256];

// vectorized no-return global reductions (sm_90+)
__device__ __forceinline__ void red_add_v4(float* p, float4 v) {
    asm volatile("red.global.add.v4.f32 [%0], {%1,%2,%3,%4};"
                 :: "l"(p), "f"(v.x), "f"(v.y), "f"(v.z), "f"(v.w) : "memory");
}
__device__ __forceinline__ void red_add_v2(float* p, float a, float b) {
    asm volatile("red.global.add.v2.f32 [%0], {%1,%2};"
                 :: "l"(p), "f"(a), "f"(b) : "memory");
}
__device__ __forceinline__ unsigned f2tf32(float f) {
    unsigned u;
    asm("cvt.rna.tf32.f32 %0, %1;" : "=r"(u) : "f"(f));
    return u;
}

// ================= CSR build =================
__global__ void hist_kernel(const int* __restrict__ row, int nnz, int* __restrict__ deg) {
    int e = blockIdx.x * blockDim.x + threadIdx.x;
    if (e < nnz) atomicAdd(&deg[__ldg(row + e)], 1);
}

__global__ void bsum_kernel(const int* __restrict__ deg, int* __restrict__ bsum) {
    int b = blockIdx.x, t = threadIdx.x;
    int i0 = b * 1024 + t * 4;
    int s = 0;
    #pragma unroll
    for (int k = 0; k < 4; k++) {
        int i = i0 + k;
        if (i < N_NODES) s += deg[i];
    }
    __shared__ int sd[256];
    sd[t] = s;
    __syncthreads();
    for (int off = 128; off > 0; off >>= 1) {
        if (t < off) sd[t] += sd[t + off];
        __syncthreads();
    }
    if (t == 0) bsum[b] = sd[0];
}

__global__ void bscan_kernel(const int* __restrict__ bsum, int* __restrict__ boffs,
                             int nb, int nnz, int* __restrict__ rowptr) {
    int t = threadIdx.x;
    __shared__ int s[256];
    int orig = (t < nb) ? bsum[t] : 0;
    s[t] = orig;
    __syncthreads();
    for (int off = 1; off < 256; off <<= 1) {
        int v = (t >= off) ? s[t - off] : 0;
        __syncthreads();
        s[t] += v;
        __syncthreads();
    }
    boffs[t] = s[t] - orig;
    if (t == 0) rowptr[N_NODES] = nnz;
}

__global__ void scan_kernel(const int* __restrict__ deg, const int* __restrict__ boffs,
                            int* __restrict__ rowptr, int* __restrict__ cursor) {
    int t = threadIdx.x;
    int lane = t & 31, wid = t >> 5;
    int i0 = blockIdx.x * 1024 + t * 4;
    int d0 = (i0 + 0 < N_NODES) ? deg[i0 + 0] : 0;
    int d1 = (i0 + 1 < N_NODES) ? deg[i0 + 1] : 0;
    int d2 = (i0 + 2 < N_NODES) ? deg[i0 + 2] : 0;
    int d3 = (i0 + 3 < N_NODES) ? deg[i0 + 3] : 0;
    int ts = d0 + d1 + d2 + d3;
    int x = ts;
    #pragma unroll
    for (int off = 1; off < 32; off <<= 1) {
        int y = __shfl_up_sync(0xffffffffu, x, off);
        if (lane >= off) x += y;
    }
    int lane_excl = x - ts;
    __shared__ int wtot[8], woff[8];
    if (lane == 31) wtot[wid] = x;
    __syncthreads();
    if (t == 0) {
        int r = 0;
        #pragma unroll
        for (int k = 0; k < 8; k++) { woff[k] = r; r += wtot[k]; }
    }
    __syncthreads();
    int p = boffs[blockIdx.x] + woff[wid] + lane_excl;
    if (i0 + 0 < N_NODES) { rowptr[i0 + 0] = p; cursor[i0 + 0] = p; } p += d0;
    if (i0 + 1 < N_NODES) { rowptr[i0 + 1] = p; cursor[i0 + 1] = p; } p += d1;
    if (i0 + 2 < N_NODES) { rowptr[i0 + 2] = p; cursor[i0 + 2] = p; } p += d2;
    if (i0 + 3 < N_NODES) { rowptr[i0 + 3] = p; cursor[i0 + 3] = p; }
}

__global__ void scatter_kernel(const int* __restrict__ row, const int* __restrict__ col,
                               const float* __restrict__ val, int nnz,
                               int* __restrict__ cursor,
                               int* __restrict__ ccol, float* __restrict__ cval) {
    int e = blockIdx.x * blockDim.x + threadIdx.x;
    if (e >= nnz) return;
    int pos = atomicAdd(&cursor[__ldg(row + e)], 1);
    ccol[pos] = __ldg(col + e);
    cval[pos] = __ldg(val + e);
}

// ================= pull SpMM =================
__global__ void pull_all_kernel(const float* __restrict__ user_rel,
                                const float* __restrict__ item_rel,
                                const int* __restrict__ rowptr,
                                const int* __restrict__ ccol, const float* __restrict__ cval,
                                float* __restrict__ dst) {
    int w = (blockIdx.x * blockDim.x + threadIdx.x) >> 5;
    int lane = threadIdx.x & 31;
    if (w >= N_NODES) return;
    int s = __ldg(rowptr + w), e = __ldg(rowptr + w + 1);
    float ax = 0.f, ay = 0.f;
    for (int j = s; j < e; j++) {
        int c = __ldg(ccol + j);
        float v = __ldg(cval + j);
        const float* src = (c < N_USER) ? user_rel + (size_t)c * DIM
                                        : item_rel + (size_t)(c - N_USER) * DIM;
        float2 x = *reinterpret_cast<const float2*>(src + lane * 2);
        ax += v * x.x; ay += v * x.y;
    }
    *reinterpret_cast<float2*>(dst + (size_t)w * DIM + lane * 2) = make_float2(ax, ay);
}

__global__ void mark2_kernel(const int* __restrict__ uid, const int* __restrict__ iid,
                             const int* __restrict__ rowptr, const int* __restrict__ ccol,
                             unsigned char* __restrict__ flag2) {
    int w = (blockIdx.x * blockDim.x + threadIdx.x) >> 5;
    int lane = threadIdx.x & 31;
    if (w >= 2 * BATCH) return;
    int node = (w < BATCH) ? __ldg(uid + w) : N_USER + __ldg(iid + w - BATCH);
    if (lane == 0) flag2[node] = 1;
    int s = __ldg(rowptr + node), e = __ldg(rowptr + node + 1);
    for (int j = s + lane; j < e; j += 32) flag2[__ldg(ccol + j)] = 1;
}

__global__ void node_compact_kernel(const unsigned char* __restrict__ flag2,
                                    int* __restrict__ list, int* __restrict__ count) {
    int n = blockIdx.x * blockDim.x + threadIdx.x;
    bool act = (n < N_NODES) && (flag2[n] != 0);
    unsigned mask = __ballot_sync(0xffffffffu, act);
    int c = __popc(mask);
    int lane = threadIdx.x & 31;
    int base = 0;
    if (lane == 0 && c) base = atomicAdd(count, c);
    base = __shfl_sync(0xffffffffu, base, 0);
    if (act) list[base + __popc(mask & ((1u << lane) - 1))] = n;
}

__global__ void pull_list_kernel(const float* __restrict__ src, float* __restrict__ dst,
                                 const int* __restrict__ rowptr,
                                 const int* __restrict__ ccol, const float* __restrict__ cval,
                                 const int* __restrict__ list, const int* __restrict__ count) {
    int nw = (gridDim.x * blockDim.x) >> 5;
    int lane = threadIdx.x & 31;
    int n = *count;
    for (int w = (blockIdx.x * blockDim.x + threadIdx.x) >> 5; w < n; w += nw) {
        int r = __ldg(list + w);
        int s = __ldg(rowptr + r), e = __ldg(rowptr + r + 1);
        float ax = 0.f, ay = 0.f;
        for (int j = s; j < e; j++) {
            int c = __ldg(ccol + j);
            float v = __ldg(cval + j);
            float2 x = *reinterpret_cast<const float2*>(src + (size_t)c * DIM + lane * 2);
            ax += v * x.x; ay += v * x.y;
        }
        *reinterpret_cast<float2*>(dst + (size_t)r * DIM + lane * 2) = make_float2(ax, ay);
    }
}

__global__ void pull_batch_kernel(const int* __restrict__ uid, const int* __restrict__ iid,
                                  const float* __restrict__ src,
                                  const int* __restrict__ rowptr,
                                  const int* __restrict__ ccol, const float* __restrict__ cval,
                                  float* __restrict__ e3) {
    int w = (blockIdx.x * blockDim.x + threadIdx.x) >> 5;
    int lane = threadIdx.x & 31;
    if (w >= 2 * BATCH) return;
    int node = (w < BATCH) ? __ldg(uid + w) : N_USER + __ldg(iid + w - BATCH);
    int s = __ldg(rowptr + node), e = __ldg(rowptr + node + 1);
    float ax = 0.f, ay = 0.f;
    for (int j = s; j < e; j++) {
        int c = __ldg(ccol + j);
        float v = __ldg(cval + j);
        float2 x = *reinterpret_cast<const float2*>(src + (size_t)c * DIM + lane * 2);
        ax += v * x.x; ay += v * x.y;
    }
    *reinterpret_cast<float2*>(e3 + (size_t)w * DIM + lane * 2) = make_float2(ax, ay);
}

// ---------------- multi-hot row sums --------------------------------------
__global__ void rowsums_kernel(const int* __restrict__ aux, float* __restrict__ sums) {
    int b = blockIdx.x;
    int t = threadIdx.x;
    const int* a = aux + (size_t)b * AUX_LD;
    float s0 = 0.f, s1 = 0.f, s2 = 0.f;
    for (int j = 1 + t;    j < 26;    j += 256) s0 += (float)a[j];
    for (int j = 26 + t;   j < 2212;  j += 256) s1 += (float)a[j];
    for (int j = 2212 + t; j < 10242; j += 256) s2 += (float)a[j];
    __shared__ float sd0[256], sd1[256], sd2[256];
    sd0[t] = s0; sd1[t] = s1; sd2[t] = s2;
    __syncthreads();
    for (int off = 128; off > 0; off >>= 1) {
        if (t < off) { sd0[t] += sd0[t + off]; sd1[t] += sd1[t + off]; sd2[t] += sd2[t + off]; }
        __syncthreads();
    }
    if (t == 0) {
        sums[b * 3 + 0] = sd0[0];
        sums[b * 3 + 1] = sd1[0];
        sums[b * 3 + 2] = sd2[0];
    }
}

// ------- multi-hot GEMM via tf32 tensor cores (R12-proven): X += (A@W)/rs --
__global__ __launch_bounds__(256)
void mh_gemm_tc_kernel(const int* __restrict__ aux, int colIn, int K, int tilesPerBlock,
                       const float* __restrict__ W,
                       const float* __restrict__ sums, int sumIdx,
                       float* __restrict__ X, int colOut) {
    __shared__ unsigned xs[64][36];   // A tile, [row][k]
    __shared__ unsigned ws[32][72];   // W tile, [k][n]
    int t = threadIdx.x;
    int wrp = t >> 5, lane = t & 31;
    int wr = wrp >> 1;
    int wc = wrp & 1;
    int rowBase = blockIdx.x * 64;
    int kStart = blockIdx.y * tilesPerBlock * 32;
    int kEnd   = min(K, kStart + tilesPerBlock * 32);

    float acc[4][4] = {};

    for (int k0 = kStart; k0 < kEnd; k0 += 32) {
        #pragma unroll
        for (int i = 0; i < 8; i++) {
            int l = t + 256 * i;
            int kk = l & 31, rr = l >> 5;
            int kg = k0 + kk;
            float a = (kg < K) ? (float)aux[(size_t)(rowBase + rr) * AUX_LD + colIn + kg] : 0.f;
            xs[rr][kk] = __float_as_uint(a);   // 0/1 exact in tf32
        }
        #pragma unroll
        for (int i = 0; i < 8; i++) {
            int l = t + 256 * i;
            int cc = l & 63, kk = l >> 6;
            int kg = k0 + kk;
            ws[kk][cc] = (kg < K) ? f2tf32(W[(size_t)kg * 64 + cc]) : 0u;
        }
        __syncthreads();
        int ar0 = wr * 16 + (lane >> 2);
        int kc  = lane & 3;
        #pragma unroll
        for (int ks = 0; ks < 32; ks += 8) {
            unsigned a0 = xs[ar0    ][ks + kc];
            unsigned a1 = xs[ar0 + 8][ks + kc];
            unsigned a2 = xs[ar0    ][ks + kc + 4];
            unsigned a3 = xs[ar0 + 8][ks + kc + 4];
            #pragma unroll
            for (int nt = 0; nt < 4; nt++) {
                int n = wc * 32 + nt * 8 + (lane >> 2);
                unsigned b0 = ws[ks + kc    ][n];
                unsigned b1 = ws[ks + kc + 4][n];
                asm volatile(
                    "mma.sync.aligned.m16n8k8.row.col.f32.tf32.tf32.f32 "
                    "{%0,%1,%2,%3}, {%4,%5,%6,%7}, {%8,%9}, {%0,%1,%2,%3};"
                    : "+f"(acc[nt][0]), "+f"(acc[nt][1]), "+f"(acc[nt][2]), "+f"(acc[nt][3])
                    : "r"(a0), "r"(a1), "r"(a2), "r"(a3), "r"(b0), "r"(b1));
            }
        }
        __syncthreads();
    }

    int r0 = rowBase + wr * 16 + (lane >> 2);
    int r1 = r0 + 8;
    float rn0 = 1.0f / sums[r0 * 3 + sumIdx];
    float rn1 = 1.0f / sums[r1 * 3 + sumIdx];
    #pragma unroll
    for (int nt = 0; nt < 4; nt++) {
        int c = colOut + wc * 32 + nt * 8 + 2 * (lane & 3);
        red_add_v2(&X[(size_t)r0 * XCOLS + c], acc[nt][0] * rn0, acc[nt][1] * rn0);
        red_add_v2(&X[(size_t)r1 * XCOLS + c], acc[nt][2] * rn1, acc[nt][3] * rn1);
    }
}

// ---------------- dense GEMM (fp32; partial sums into pre-zeroed out) -----
__global__ __launch_bounds__(256)
void fc_gemm_kernel(const float* __restrict__ A, int lda, int K, int tilesPerBlock,
                    const float* __restrict__ W, float* __restrict__ out, int ldo) {
    __shared__ float xs[32][68];
    __shared__ float ws[32][64];
    int t  = threadIdx.x;
    int tx = t & 15;
    int ty = t >> 4;
    int rowBase = blockIdx.x * 64;
    int kStart = blockIdx.y * tilesPerBlock * 32;
    int kEnd   = min(K, kStart + tilesPerBlock * 32);

    float acc[4][4] = {};
    for (int k0 = kStart; k0 < kEnd; k0 += 32) {
        #pragma unroll
        for (int i = 0; i < 8; i++) {
            int l = t + 256 * i;
            int kk = l & 31, rr = l >> 5;
            int kg = k0 + kk;
            xs[kk][rr] = (kg < K) ? A[(size_t)(rowBase + rr) * lda + kg] : 0.f;
        }
        #pragma unroll
        for (int i = 0; i < 8; i++) {
            int l = t + 256 * i;
            int cc = l & 63, kk = l >> 6;
            int kg = k0 + kk;
            ws[kk][cc] = (kg < K) ? W[(size_t)kg * 64 + cc] : 0.f;
        }
        __syncthreads();
        #pragma unroll
        for (int k = 0; k < 32; k++) {
            float4 wv = *reinterpret_cast<float4*>(&ws[k][tx * 4]);
            float4 av = *reinterpret_cast<float4*>(&xs[k][ty * 4]);
            acc[0][0] += av.x * wv.x; acc[0][1] += av.x * wv.y; acc[0][2] += av.x * wv.z; acc[0][3] += av.x * wv.w;
            acc[1][0] += av.y * wv.x; acc[1][1] += av.y * wv.y; acc[1][2] += av.y * wv.z; acc[1][3] += av.y * wv.w;
            acc[2][0] += av.z * wv.x; acc[2][1] += av.z * wv.y; acc[2][2] += av.z * wv.z; acc[2][3] += av.z * wv.w;
            acc[3][0] += av.w * wv.x; acc[3][1] += av.w * wv.y; acc[3][2] += av.w * wv.z; acc[3][3] += av.w * wv.w;
        }
        __syncthreads();
    }
    #pragma unroll
    for (int r = 0; r < 4; r++) {
        int row = rowBase + ty * 4 + r;
        float4 v = make_float4(acc[r][0], acc[r][1], acc[r][2], acc[r][3]);
        red_add_v4(&out[(size_t)row * ldo + tx * 4], v);
    }
}

__global__ void bias_act_kernel(float* __restrict__ h, const float* __restrict__ b, int n) {
    int i = blockIdx.x * blockDim.x + threadIdx.x;
    if (i >= n) return;
    float v = h[i] + b[i & 63];
    h[i] = v > 0.f ? v : 0.f;
}

// ---------------- gathers: tables + LightGCN sum (emb0+e1+e2+e3)/4 --------
__global__ void gather_kernel(const int* __restrict__ aux,
                              const int* __restrict__ uid, const int* __restrict__ iid,
                              const float* __restrict__ rate_tab,
                              const float* __restrict__ gender_tab,
                              const float* __restrict__ age_tab,
                              const float* __restrict__ occ_tab,
                              const float* __restrict__ area_tab,
                              const float* __restrict__ user_rel,
                              const float* __restrict__ item_rel,
                              const float* __restrict__ e1,
                              const float* __restrict__ e2,
                              const float* __restrict__ e3,
                              float* __restrict__ X) {
    int b = blockIdx.x;
    int d = threadIdx.x;   // 64
    const int* a = aux + (size_t)b * AUX_LD;
    float* xr = X + (size_t)b * XCOLS;
    xr[0   + d] = rate_tab  [(size_t)a[0]     * 64 + d];
    xr[256 + d] = gender_tab[(size_t)a[10242] * 64 + d];
    xr[320 + d] = age_tab   [(size_t)a[10243] * 64 + d];
    xr[384 + d] = occ_tab   [(size_t)a[10244] * 64 + d];
    xr[448 + d] = area_tab  [(size_t)a[10245] * 64 + d];
    int u  = uid[b];
    int it = iid[b];
    size_t un  = (size_t)u * 64 + d;
    size_t in_ = ((size_t)N_USER + it) * 64 + d;
    xr[512 + d] = 0.25f * (user_rel[un] + e1[un] + e2[un] + e3[(size_t)b * 64 + d]);
    xr[576 + d] = 0.25f * (item_rel[(size_t)it * 64 + d] + e1[in_] + e2[in_]
                           + e3[(size_t)(BATCH + b) * 64 + d]);
}

// ---------------- final dot -----------------------------------------------
__global__ void out_kernel(const float* __restrict__ H2, const float* __restrict__ w,
                           const float* __restrict__ ob, float* __restrict__ out) {
    int b = blockIdx.x;
    int t = threadIdx.x;   // 64
    __shared__ float s[64];
    s[t] = H2[(size_t)b * 64 + t] * w[t];
    __syncthreads();
    for (int off = 32; off > 0; off >>= 1) {
        if (t < off) s[t] += s[t + off];
        __syncthreads();
    }
    if (t == 0) out[b] = s[0] + ob[0];
}

// ---------------- launch ---------------------------------------------------
extern "C" void kernel_launch(void* const* d_in, const int* in_sizes, int n_in,
                              void* d_out, int out_size) {
    const int*   aux       = (const int*)  d_in[0];
    const int*   user_ids  = (const int*)  d_in[1];
    const int*   item_ids  = (const int*)  d_in[2];
    const int*   grow      = (const int*)  d_in[3];
    const int*   gcol      = (const int*)  d_in[4];
    const float* gval      = (const float*)d_in[5];
    const float* rate_tab  = (const float*)d_in[6];
    const float* genre_W   = (const float*)d_in[7];
    const float* director_W= (const float*)d_in[8];
    const float* actor_W   = (const float*)d_in[9];
    const float* gender_tab= (const float*)d_in[10];
    const float* age_tab   = (const float*)d_in[11];
    const float* occ_tab   = (const float*)d_in[12];
    const float* area_tab  = (const float*)d_in[13];
    const float* user_rel  = (const float*)d_in[14];
    const float* item_rel  = (const float*)d_in[15];
    const float* fc1_W     = (const float*)d_in[16];
    const float* fc1_b     = (const float*)d_in[17];
    const float* fc2_W     = (const float*)d_in[18];
    const float* fc2_b     = (const float*)d_in[19];
    const float* out_W     = (const float*)d_in[20];
    const float* out_b     = (const float*)d_in[21];
    int nnz = in_sizes[3];

    float *embB, *embC, *e3, *X, *H1, *H2, *sums;
    unsigned char* flag2;
    int *nlist2, *cnt, *deg, *rowptr, *cursor, *ccol, *bsum, *boffs;
    float* cval;
    cudaGetSymbolAddress((void**)&embB,  g_embB);
    cudaGetSymbolAddress((void**)&embC,  g_embC);
    cudaGetSymbolAddress((void**)&e3,    g_e3);
    cudaGetSymbolAddress((void**)&X,     g_X);
    cudaGetSymbolAddress((void**)&H1,    g_H1);
    cudaGetSymbolAddress((void**)&H2,    g_H2);
    cudaGetSymbolAddress((void**)&sums,  g_sums);
    cudaGetSymbolAddress((void**)&flag2, g_flag2);
    cudaGetSymbolAddress((void**)&nlist2,g_nlist2);
    cudaGetSymbolAddress((void**)&cnt,   g_cnt);
    cudaGetSymbolAddress((void**)&deg,   g_deg);
    cudaGetSymbolAddress((void**)&rowptr,g_rowptr);
    cudaGetSymbolAddress((void**)&cursor,g_cursor);
    cudaGetSymbolAddress((void**)&ccol,  g_csr_col);
    cudaGetSymbolAddress((void**)&cval,  g_csr_val);
    cudaGetSymbolAddress((void**)&bsum,  g_bsum);
    cudaGetSymbolAddress((void**)&boffs, g_boffs);

    const int EB = (nnz + 255) / 256;
    const int NB = (N_NODES + 1023) / 1024;   // 176

    // --- side stream + fork/join events (host objects; created once) ---
    static cudaStream_t s_mh = nullptr;
    static cudaEvent_t evFork = nullptr, evJoin = nullptr;
    if (s_mh == nullptr) {
        cudaStreamCreateWithFlags(&s_mh, cudaStreamNonBlocking);
        cudaEventCreateWithFlags(&evFork, cudaEventDisableTiming);
        cudaEventCreateWithFlags(&evJoin, cudaEventDisableTiming);
    }

    // fork: side stream inherits capture dependency from main stream
    cudaEventRecord(evFork, (cudaStream_t)0);
    cudaStreamWaitEvent(s_mh, evFork, 0);

    // ===== Chain A (side stream): multi-hot path =====
    cudaMemsetAsync(X, 0, (size_t)BATCH * XCOLS * sizeof(float), s_mh);
    rowsums_kernel<<<BATCH, 256, 0, s_mh>>>(aux, sums);
    mh_gemm_tc_kernel<<<dim3(16, 1),  256, 0, s_mh>>>(aux, 1,    25,   1, genre_W,    sums, 0, X, 64);
    mh_gemm_tc_kernel<<<dim3(16, 14), 256, 0, s_mh>>>(aux, 26,   2186, 5, director_W, sums, 1, X, 128);
    mh_gemm_tc_kernel<<<dim3(16, 28), 256, 0, s_mh>>>(aux, 2212, 8030, 9, actor_W,    sums, 2, X, 192);
    cudaEventRecord(evJoin, s_mh);

    // ===== Chain B (main stream): CSR + LightGCN pulls =====
    cudaMemsetAsync(deg, 0, N_NODES * sizeof(int));
    cudaMemsetAsync(flag2, 0, N_NODES);
    cudaMemsetAsync(cnt, 0, 4 * sizeof(int));
    cudaMemsetAsync(H1, 0, (size_t)BATCH * DIM * sizeof(float));
    cudaMemsetAsync(H2, 0, (size_t)BATCH * DIM * sizeof(float));
    hist_kernel<<<EB, 256>>>(grow, nnz, deg);
    bsum_kernel<<<NB, 256>>>(deg, bsum);
    bscan_kernel<<<1, 256>>>(bsum, boffs, NB, nnz, rowptr);
    scan_kernel<<<NB, 256>>>(deg, boffs, rowptr, cursor);
    scatter_kernel<<<EB, 256>>>(grow, gcol, gval, nnz, cursor, ccol, cval);

    mark2_kernel<<<(2 * BATCH * 32 + 255) / 256, 256>>>(user_ids, item_ids, rowptr, ccol, flag2);
    node_compact_kernel<<<(N_NODES + 255) / 256, 256>>>(flag2, nlist2, cnt + 0);

    pull_all_kernel<<<(N_NODES * 32 + 255) / 256, 256>>>(user_rel, item_rel,
                                                         rowptr, ccol, cval, embB);
    pull_list_kernel<<<2048, 256>>>(embB, embC, rowptr, ccol, cval, nlist2, cnt + 0);
    pull_batch_kernel<<<(2 * BATCH * 32 + 255) / 256, 256>>>(user_ids, item_ids, embC,
                                                             rowptr, ccol, cval, e3);

    // gather writes X cols [0,64) and [256,640) — disjoint from chain A's [64,256)
    gather_kernel<<<BATCH, 64>>>(aux, user_ids, item_ids, rate_tab, gender_tab,
                                 age_tab, occ_tab, area_tab,
                                 user_rel, item_rel, embB, embC, e3, X);

    // join: fc1 reads the whole X
    cudaStreamWaitEvent((cudaStream_t)0, evJoin, 0);

    // --- MLP (R12-proven fp32 path) ---
    fc_gemm_kernel<<<dim3(16, 20), 256>>>(X, XCOLS, XCOLS, 1, fc1_W, H1, 64);
    bias_act_kernel<<<(BATCH * DIM + 255) / 256, 256>>>(H1, fc1_b, BATCH * DIM);

    fc_gemm_kernel<<<dim3(16, 2), 256>>>(H1, 64, 64, 1, fc2_W, H2, 64);
    bias_act_kernel<<<(BATCH * DIM + 255) / 256, 256>>>(H2, fc2_b, BATCH * DIM);

    out_kernel<<<BATCH, 64>>>(H2, out_W, out_b, (float*)d_out);
}